// round 16
// baseline (speedup 1.0000x reference)
#include <cuda_runtime.h>
#include <cuda_bf16.h>
#include <cstdint>

#define B_ 16
#define T_ 4096
#define D_ 512
#define R_ 256

// NOTE: g_Q*/g_K* rows are stored k-PERMUTED within 16-groups:
//   pos(k) = (k & ~15) + 4*((k>>1)&3) + (k&1) + 2*((k>>3)&1)
// so the m16n8k16 fragment quad {2c4, 2c4+1, 2c4+8, 2c4+9} is contiguous (LDS.64).
__device__ __nv_bfloat16 g_Qhi[(size_t)B_ * T_ * D_];  // 64 MB
__device__ __nv_bfloat16 g_Qlo[(size_t)B_ * T_ * D_];  // 64 MB
__device__ __nv_bfloat16 g_Khi[(size_t)B_ * R_ * D_];  // 4 MB
__device__ __nv_bfloat16 g_Klo[(size_t)B_ * R_ * D_];  // 4 MB
__device__ float g_W [(size_t)T_ * R_];                // mask * exp(-a*tdist)
__device__ float g_alpha[3];

__device__ __forceinline__ long long lm_of(int r) {
    // numpy linspace(0,4095,256).astype(int64), exact
    return (r == 255) ? 4095LL : (long long)((double)r * (4095.0 / 255.0));
}

// ---------------- kernel 1: W table + alpha (absorbs old prep) --------------
__global__ void w_kernel(const float* __restrict__ gw, const float* __restrict__ ta) {
    int t = blockIdx.x, r = threadIdx.x;
    if (blockIdx.x == 0 && r == 0) {
        float w0 = gw[0], w1 = gw[1], w2 = gw[2];
        float m = fmaxf(w0, fmaxf(w1, w2));
        float e0 = expf(w0 - m), e1 = expf(w1 - m), e2 = expf(w2 - m);
        float s = e0 + e1 + e2;
        g_alpha[0] = e0 / s; g_alpha[1] = e1 / s; g_alpha[2] = e2 / s;
    }
    float x = ta[0];
    float atd = fmaxf(x, 0.0f) + log1pf(expf(-fabsf(x)));   // softplus
    long long lm = lm_of(r);
    float w = 0.0f;
    if (lm < t) {
        float td = ((float)t - (float)lm) * (1.0f / 4096.0f);
        w = expf(-atd * td);
    }
    g_W[(size_t)t * R_ + r] = w;
}

__device__ __forceinline__ int ppair(int k) {   // position of even-k pair start
    return (k & ~15) + 4 * ((k >> 1) & 3) + 2 * ((k >> 3) & 1);
}

// ------- kernel 2: normalize -> bf16 hi/lo (permuted) + landmark scatter -----
__global__ void norm_kernel(const float* __restrict__ z) {
    int row = blockIdx.x;                 // b*T + t
    size_t base = (size_t)row * D_;
    int tid = threadIdx.x;                // 128 threads, 4 floats each
    float4 v = reinterpret_cast<const float4*>(z + base)[tid];
    float ss = v.x * v.x + v.y * v.y + v.z * v.z + v.w * v.w;
    #pragma unroll
    for (int o = 16; o > 0; o >>= 1) ss += __shfl_xor_sync(0xffffffffu, ss, o);
    __shared__ float ws[4];
    if ((tid & 31) == 0) ws[tid >> 5] = ss;
    __syncthreads();
    float tot = ws[0] + ws[1] + ws[2] + ws[3];
    float inv = 1.0f / fmaxf(sqrtf(tot), 1e-12f);
    float q[4] = {v.x * inv, v.y * inv, v.z * inv, v.w * inv};
    uint32_t hp[2], lp[2];
    #pragma unroll
    for (int i = 0; i < 2; i++) {
        __nv_bfloat16 h0 = __float2bfloat16_rn(q[2*i]);
        __nv_bfloat16 h1 = __float2bfloat16_rn(q[2*i+1]);
        __nv_bfloat16 l0 = __float2bfloat16_rn(q[2*i]   - __bfloat162float(h0));
        __nv_bfloat16 l1 = __float2bfloat16_rn(q[2*i+1] - __bfloat162float(h1));
        hp[i] = ((uint32_t)__bfloat16_as_ushort(h1) << 16) | __bfloat16_as_ushort(h0);
        lp[i] = ((uint32_t)__bfloat16_as_ushort(l1) << 16) | __bfloat16_as_ushort(l0);
    }
    int k0 = 4 * tid;
    int p0 = ppair(k0), p1 = ppair(k0 + 2);
    *reinterpret_cast<uint32_t*>(&g_Qhi[base + p0]) = hp[0];
    *reinterpret_cast<uint32_t*>(&g_Qhi[base + p1]) = hp[1];
    *reinterpret_cast<uint32_t*>(&g_Qlo[base + p0]) = lp[0];
    *reinterpret_cast<uint32_t*>(&g_Qlo[base + p1]) = lp[1];

    // landmark scatter: if t == lm(r) for some r, also write the K row
    int t = row & (T_ - 1), b = row >> 12;
    int r0 = (t * 255) / 4095;
    int rl = -1;
    #pragma unroll
    for (int d = 0; d < 2; d++) {
        int rr = r0 + d;
        if (rr < 256 && lm_of(rr) == (long long)t) rl = rr;
    }
    if (rl >= 0) {
        size_t kb = ((size_t)(b * R_ + rl)) * D_;
        *reinterpret_cast<uint32_t*>(&g_Khi[kb + p0]) = hp[0];
        *reinterpret_cast<uint32_t*>(&g_Khi[kb + p1]) = hp[1];
        *reinterpret_cast<uint32_t*>(&g_Klo[kb + p0]) = lp[0];
        *reinterpret_cast<uint32_t*>(&g_Klo[kb + p1]) = lp[1];
    }
}

// ---------------- kernel 3: fused GEMM + epilogue (3x bf16, m16n8k16) --------
// Mainloop structure identical to R13 (299.0 us): 2-stage, load-before-wait,
// two __syncthreads per iteration. Do not restructure (R14 regression).
#define BM 128
#define BN 256
#define BKC 32                         /* K per stage */
#define STRB 48                        /* bf16 per row: 32 data + 16 pad (96B) */
#define A_T (BM * STRB)                /* 6144 bf16 */
#define B_T (BN * STRB)                /* 12288 bf16 */
#define BUF (2 * A_T + 2 * B_T)        /* 36864 bf16 = 73728 B per stage */
#define SMEM_BYTES (2 * BUF * 2)       /* 147456 B */

__device__ __forceinline__ void cp16(uint32_t sdst, const void* gsrc) {
    asm volatile("cp.async.cg.shared.global [%0], [%1], 16;" :: "r"(sdst), "l"(gsrc));
}

__device__ __forceinline__ void mma_bf16(float* acc,
                                         uint32_t a0, uint32_t a1, uint32_t a2, uint32_t a3,
                                         uint32_t b0, uint32_t b1) {
    asm volatile(
        "mma.sync.aligned.m16n8k16.row.col.f32.bf16.bf16.f32 "
        "{%0,%1,%2,%3}, {%4,%5,%6,%7}, {%8,%9}, {%0,%1,%2,%3};"
        : "+f"(acc[0]), "+f"(acc[1]), "+f"(acc[2]), "+f"(acc[3])
        : "r"(a0), "r"(a1), "r"(a2), "r"(a3), "r"(b0), "r"(b1));
}

__device__ __forceinline__ float gphi(float C, float A0, float A1, float A2) {
    float C2 = C * C;
    float P1 = 0.5f * (1.0f + C);
    float P2 = 0.5f * (3.0f * C2 - 1.0f);
    float P3 = 0.5f * (5.0f * C2 * C - 3.0f * C);
    return A0 * P1 + A1 * P2 + A2 * P3;
}

__global__ void __launch_bounds__(512) gemm_kernel(float* __restrict__ out) {
    extern __shared__ __nv_bfloat16 sm[];
    __shared__ float red[4][BM];          // per-wn partial row sums

    uint32_t smb = (uint32_t)__cvta_generic_to_shared(sm);
    int tid = threadIdx.x;
    int b  = blockIdx.y;
    int t0 = blockIdx.x * BM;
    const __nv_bfloat16* Ahg = g_Qhi + ((size_t)b * T_ + t0) * D_;
    const __nv_bfloat16* Alg = g_Qlo + ((size_t)b * T_ + t0) * D_;
    const __nv_bfloat16* Bhg = g_Khi + (size_t)b * R_ * D_;
    const __nv_bfloat16* Blg = g_Klo + (size_t)b * R_ * D_;

    int warp = tid >> 5, lane = tid & 31;
    int wm = warp >> 2, wn = warp & 3;    // 4 x 4 warp grid: 32 rows x 64 cols each
    int r4 = lane >> 2, c4 = lane & 3;

    float acc[2][8][4];
    #pragma unroll
    for (int mi = 0; mi < 2; mi++)
        #pragma unroll
        for (int j = 0; j < 8; j++)
            #pragma unroll
            for (int e = 0; e < 4; e++) acc[mi][j][e] = 0.f;

    // cp.async mapping: rows of 64B data (4 x 16B chunks) in 96B-stride smem rows
    int arow = tid >> 2, au = tid & 3;    // A: 512 chunks -> 1/thread (each of hi/lo)

    // prefetch k-tile 0
    {
        uint32_t adst = smb + (uint32_t)(arow * 96 + au * 16);
        size_t g = (size_t)arow * D_ + au * 8;
        cp16(adst,             Ahg + g);
        cp16(adst + 2 * A_T,   Alg + g);          // Alo region (bytes = A_T*2)
        #pragma unroll
        for (int i = 0; i < 2; i++) {             // B: 1024 chunks each -> 2/thread
            int c = tid + i * 512; int row = c >> 2, u = c & 3;
            uint32_t bdst = smb + 4 * A_T + (uint32_t)(row * 96 + u * 16);
            size_t gb = (size_t)row * D_ + u * 8;
            cp16(bdst,           Bhg + gb);
            cp16(bdst + 2 * B_T, Blg + gb);
        }
    }
    asm volatile("cp.async.commit_group;");

    const int KI = D_ / BKC;   // 16
    for (int kt = 0; kt < KI; kt++) {
        int buf = kt & 1;
        if (kt + 1 < KI) {
            int nb = buf ^ 1; int k0 = (kt + 1) * BKC;
            uint32_t base = smb + (uint32_t)nb * (BUF * 2);
            uint32_t adst = base + (uint32_t)(arow * 96 + au * 16);
            size_t g = (size_t)arow * D_ + k0 + au * 8;
            cp16(adst,           Ahg + g);
            cp16(adst + 2 * A_T, Alg + g);
            #pragma unroll
            for (int i = 0; i < 2; i++) {
                int c = tid + i * 512; int row = c >> 2, u = c & 3;
                uint32_t bdst = base + 4 * A_T + (uint32_t)(row * 96 + u * 16);
                size_t gb = (size_t)row * D_ + k0 + u * 8;
                cp16(bdst,           Bhg + gb);
                cp16(bdst + 2 * B_T, Blg + gb);
            }
            asm volatile("cp.async.commit_group;");
            asm volatile("cp.async.wait_group 1;");
        } else {
            asm volatile("cp.async.wait_group 0;");
        }
        __syncthreads();

        const __nv_bfloat16* Ah = sm + (size_t)buf * BUF + (wm * 32) * STRB;
        const __nv_bfloat16* Al = Ah + A_T;
        const __nv_bfloat16* Bh = sm + (size_t)buf * BUF + 2 * A_T + (wn * 64) * STRB;
        const __nv_bfloat16* Bl = Bh + B_T;
        #pragma unroll
        for (int s = 0; s < 2; s++) {             // two k16 steps per BKC=32
            int kq = s * 16 + c4 * 4;             // quad {2c4,2c4+1,2c4+8,2c4+9}
            uint2 ah0 = *reinterpret_cast<const uint2*>(&Ah[(r4)      * STRB + kq]);
            uint2 ah1 = *reinterpret_cast<const uint2*>(&Ah[(r4 + 8)  * STRB + kq]);
            uint2 ah2 = *reinterpret_cast<const uint2*>(&Ah[(r4 + 16) * STRB + kq]);
            uint2 ah3 = *reinterpret_cast<const uint2*>(&Ah[(r4 + 24) * STRB + kq]);
            uint2 al0 = *reinterpret_cast<const uint2*>(&Al[(r4)      * STRB + kq]);
            uint2 al1 = *reinterpret_cast<const uint2*>(&Al[(r4 + 8)  * STRB + kq]);
            uint2 al2 = *reinterpret_cast<const uint2*>(&Al[(r4 + 16) * STRB + kq]);
            uint2 al3 = *reinterpret_cast<const uint2*>(&Al[(r4 + 24) * STRB + kq]);
            #pragma unroll
            for (int j = 0; j < 8; j++) {
                int ro = (j * 8 + r4) * STRB + kq;
                uint2 bh = *reinterpret_cast<const uint2*>(&Bh[ro]);
                uint2 bl = *reinterpret_cast<const uint2*>(&Bl[ro]);
                // hi*hi + hi*lo + lo*hi
                mma_bf16(acc[0][j], ah0.x, ah1.x, ah0.y, ah1.y, bh.x, bh.y);
                mma_bf16(acc[0][j], ah0.x, ah1.x, ah0.y, ah1.y, bl.x, bl.y);
                mma_bf16(acc[0][j], al0.x, al1.x, al0.y, al1.y, bh.x, bh.y);
                mma_bf16(acc[1][j], ah2.x, ah3.x, ah2.y, ah3.y, bh.x, bh.y);
                mma_bf16(acc[1][j], ah2.x, ah3.x, ah2.y, ah3.y, bl.x, bl.y);
                mma_bf16(acc[1][j], al2.x, al3.x, al2.y, al3.y, bh.x, bh.y);
            }
        }
        __syncthreads();
    }

    // ---------------- fused epilogue ----------------
    float A0 = g_alpha[0], A1 = g_alpha[1], A2 = g_alpha[2];
    int colb = wn * 64 + c4 * 2;
    float sums[2][2] = {{0.f, 0.f}, {0.f, 0.f}};
    #pragma unroll
    for (int mi = 0; mi < 2; mi++) {
        int gr0 = t0 + wm * 32 + mi * 16 + r4;
        const float* W0 = g_W + (size_t)gr0 * R_;
        const float* W1 = W0 + 8 * R_;
        #pragma unroll
        for (int j = 0; j < 8; j++) {
            int col = colb + j * 8;
            float p;
            p = gphi(acc[mi][j][0], A0, A1, A2) * W0[col];     acc[mi][j][0] = p; sums[mi][0] += p;
            p = gphi(acc[mi][j][1], A0, A1, A2) * W0[col + 1]; acc[mi][j][1] = p; sums[mi][0] += p;
            p = gphi(acc[mi][j][2], A0, A1, A2) * W1[col];     acc[mi][j][2] = p; sums[mi][1] += p;
            p = gphi(acc[mi][j][3], A0, A1, A2) * W1[col + 1]; acc[mi][j][3] = p; sums[mi][1] += p;
        }
    }
    #pragma unroll
    for (int mi = 0; mi < 2; mi++)
        #pragma unroll
        for (int e = 0; e < 2; e++) {
            sums[mi][e] += __shfl_xor_sync(0xffffffffu, sums[mi][e], 1);
            sums[mi][e] += __shfl_xor_sync(0xffffffffu, sums[mi][e], 2);
        }
    if (c4 == 0) {
        #pragma unroll
        for (int mi = 0; mi < 2; mi++) {
            red[wn][wm * 32 + mi * 16 + r4]     = sums[mi][0];
            red[wn][wm * 32 + mi * 16 + r4 + 8] = sums[mi][1];
        }
    }
    __syncthreads();

    #pragma unroll
    for (int mi = 0; mi < 2; mi++) {
        #pragma unroll
        for (int e = 0; e < 2; e++) {
            int lrow = wm * 32 + mi * 16 + r4 + 8 * e;
            float tot = red[0][lrow] + red[1][lrow] + red[2][lrow] + red[3][lrow];
            float inv = 1.0f / fmaxf(tot, 1e-6f);
            float* o = out + ((size_t)b * T_ + t0 + lrow) * (R_ + 1);
            #pragma unroll
            for (int j = 0; j < 8; j++) {
                int col = colb + j * 8;
                o[col]     = acc[mi][j][2 * e]     * inv;
                o[col + 1] = acc[mi][j][2 * e + 1] * inv;
            }
            if (wn == 0 && c4 == 0) o[R_] = 1.0f;
        }
    }
}

// ---------------- launch ----------------
extern "C" void kernel_launch(void* const* d_in, const int* in_sizes, int n_in,
                              void* d_out, int out_size) {
    const float* z  = (const float*)d_in[0];
    const float* gw = (const float*)d_in[1];
    const float* ta = (const float*)d_in[2];
    float* out = (float*)d_out;

    w_kernel<<<T_, R_>>>(gw, ta);
    norm_kernel<<<B_ * T_, 128>>>(z);

    cudaFuncSetAttribute(gemm_kernel, cudaFuncAttributeMaxDynamicSharedMemorySize, SMEM_BYTES);
    gemm_kernel<<<dim3(T_ / BM, B_), 512, SMEM_BYTES>>>(out);
}

// round 17
// speedup vs baseline: 1.1661x; 1.1661x over previous
#include <cuda_runtime.h>
#include <cuda_bf16.h>
#include <cstdint>

#define B_ 16
#define T_ 4096
#define D_ 512
#define R_ 256

// NOTE: g_Q*/g_K* rows are stored k-PERMUTED within 16-groups:
//   pos(k) = (k & ~15) + 4*((k>>1)&3) + (k&1) + 2*((k>>3)&1)
// so the m16n8k16 fragment quad {2c4, 2c4+1, 2c4+8, 2c4+9} is contiguous (LDS.64).
__device__ __nv_bfloat16 g_Qhi[(size_t)B_ * T_ * D_];  // 64 MB
__device__ __nv_bfloat16 g_Qlo[(size_t)B_ * T_ * D_];  // 64 MB
__device__ __nv_bfloat16 g_Khi[(size_t)B_ * R_ * D_];  // 4 MB
__device__ __nv_bfloat16 g_Klo[(size_t)B_ * R_ * D_];  // 4 MB
__device__ float g_W [(size_t)T_ * R_];                // mask * exp(-a*tdist)
__device__ int   g_lm[R_];
__device__ float g_alpha[3];
__device__ float g_atd;

// ---------------- kernel 1: scalars + landmarks ----------------
__global__ void prep_kernel(const float* __restrict__ gw, const float* __restrict__ ta) {
    int i = threadIdx.x;
    if (i < R_) {
        double delta = 4095.0 / 255.0;            // numpy linspace exact
        long long v = (long long)((double)i * delta);
        if (i == R_ - 1) v = 4095;
        g_lm[i] = (int)v;
    }
    if (i == 0) {
        float w0 = gw[0], w1 = gw[1], w2 = gw[2];
        float m = fmaxf(w0, fmaxf(w1, w2));
        float e0 = expf(w0 - m), e1 = expf(w1 - m), e2 = expf(w2 - m);
        float s = e0 + e1 + e2;
        g_alpha[0] = e0 / s; g_alpha[1] = e1 / s; g_alpha[2] = e2 / s;
        float x = ta[0];
        g_atd = fmaxf(x, 0.0f) + log1pf(expf(-fabsf(x)));   // softplus
    }
}

// ---------------- kernel 2: W[t][r] = mask * exp(-a*tdist) ----------------
__global__ void w_kernel() {
    int t = blockIdx.x, r = threadIdx.x;
    int lm = g_lm[r];
    float w = 0.0f;
    if (lm < t) {
        float td = ((float)t - (float)lm) * (1.0f / 4096.0f);
        w = expf(-g_atd * td);
    }
    g_W[(size_t)t * R_ + r] = w;
}

__device__ __forceinline__ int ppair(int k) {   // position of even-k pair start
    return (k & ~15) + 4 * ((k >> 1) & 3) + 2 * ((k >> 3) & 1);
}

// ---------------- kernel 3: normalize z rows -> bf16 hi/lo, permuted ---------
__global__ void norm_kernel(const float* __restrict__ z) {
    int row = blockIdx.x;                 // 0 .. B*T-1
    size_t base = (size_t)row * D_;
    int tid = threadIdx.x;                // 128 threads, 4 floats each
    float4 v = reinterpret_cast<const float4*>(z + base)[tid];
    float ss = v.x * v.x + v.y * v.y + v.z * v.z + v.w * v.w;
    #pragma unroll
    for (int o = 16; o > 0; o >>= 1) ss += __shfl_xor_sync(0xffffffffu, ss, o);
    __shared__ float ws[4];
    if ((tid & 31) == 0) ws[tid >> 5] = ss;
    __syncthreads();
    float tot = ws[0] + ws[1] + ws[2] + ws[3];
    float inv = 1.0f / fmaxf(sqrtf(tot), 1e-12f);
    float q[4] = {v.x * inv, v.y * inv, v.z * inv, v.w * inv};
    uint32_t hp[2], lp[2];
    #pragma unroll
    for (int i = 0; i < 2; i++) {
        __nv_bfloat16 h0 = __float2bfloat16_rn(q[2*i]);
        __nv_bfloat16 h1 = __float2bfloat16_rn(q[2*i+1]);
        __nv_bfloat16 l0 = __float2bfloat16_rn(q[2*i]   - __bfloat162float(h0));
        __nv_bfloat16 l1 = __float2bfloat16_rn(q[2*i+1] - __bfloat162float(h1));
        hp[i] = ((uint32_t)__bfloat16_as_ushort(h1) << 16) | __bfloat16_as_ushort(h0);
        lp[i] = ((uint32_t)__bfloat16_as_ushort(l1) << 16) | __bfloat16_as_ushort(l0);
    }
    int k0 = 4 * tid;
    int p0 = ppair(k0), p1 = ppair(k0 + 2);
    *reinterpret_cast<uint32_t*>(&g_Qhi[base + p0]) = hp[0];
    *reinterpret_cast<uint32_t*>(&g_Qhi[base + p1]) = hp[1];
    *reinterpret_cast<uint32_t*>(&g_Qlo[base + p0]) = lp[0];
    *reinterpret_cast<uint32_t*>(&g_Qlo[base + p1]) = lp[1];
}

// ---------------- kernel 4: gather landmark rows (positional copy) -----------
__global__ void gather_kernel() {
    int rowid = blockIdx.x;               // b*R + r
    int b = rowid >> 8, r = rowid & 255;
    int lm = g_lm[r];
    size_t s = ((size_t)(b * T_ + lm)) * D_;
    size_t d = (size_t)rowid * D_;
    reinterpret_cast<uint2*>(g_Khi + d)[threadIdx.x] =
        reinterpret_cast<const uint2*>(g_Qhi + s)[threadIdx.x];
    reinterpret_cast<uint2*>(g_Klo + d)[threadIdx.x] =
        reinterpret_cast<const uint2*>(g_Qlo + s)[threadIdx.x];
}

// ---------------- kernel 5: fused GEMM + epilogue (3x bf16, m16n8k16) --------
#define BM 128
#define BN 256
#define BKC 32                         /* K per stage */
#define STRB 48                        /* bf16 per row: 32 data + 16 pad (96B) */
#define A_T (BM * STRB)                /* 6144 bf16 */
#define B_T (BN * STRB)                /* 12288 bf16 */
#define BUF (2 * A_T + 2 * B_T)        /* 36864 bf16 = 73728 B per stage */
#define SMEM_BYTES (2 * BUF * 2)       /* 147456 B */

__device__ __forceinline__ void cp16(uint32_t sdst, const void* gsrc) {
    asm volatile("cp.async.cg.shared.global [%0], [%1], 16;" :: "r"(sdst), "l"(gsrc));
}

__device__ __forceinline__ void mma_bf16(float* acc,
                                         uint32_t a0, uint32_t a1, uint32_t a2, uint32_t a3,
                                         uint32_t b0, uint32_t b1) {
    asm volatile(
        "mma.sync.aligned.m16n8k16.row.col.f32.bf16.bf16.f32 "
        "{%0,%1,%2,%3}, {%4,%5,%6,%7}, {%8,%9}, {%0,%1,%2,%3};"
        : "+f"(acc[0]), "+f"(acc[1]), "+f"(acc[2]), "+f"(acc[3])
        : "r"(a0), "r"(a1), "r"(a2), "r"(a3), "r"(b0), "r"(b1));
}

__device__ __forceinline__ float gphi(float C, float A0, float A1, float A2) {
    float C2 = C * C;
    float P1 = 0.5f * (1.0f + C);
    float P2 = 0.5f * (3.0f * C2 - 1.0f);
    float P3 = 0.5f * (5.0f * C2 * C - 3.0f * C);
    return A0 * P1 + A1 * P2 + A2 * P3;
}

__global__ void __launch_bounds__(512) gemm_kernel(float* __restrict__ out) {
    extern __shared__ __nv_bfloat16 sm[];
    __shared__ float red[4][BM];          // per-wn partial row sums

    uint32_t smb = (uint32_t)__cvta_generic_to_shared(sm);
    int tid = threadIdx.x;
    int b  = blockIdx.y;
    int t0 = blockIdx.x * BM;
    const __nv_bfloat16* Ahg = g_Qhi + ((size_t)b * T_ + t0) * D_;
    const __nv_bfloat16* Alg = g_Qlo + ((size_t)b * T_ + t0) * D_;
    const __nv_bfloat16* Bhg = g_Khi + (size_t)b * R_ * D_;
    const __nv_bfloat16* Blg = g_Klo + (size_t)b * R_ * D_;

    int warp = tid >> 5, lane = tid & 31;
    int wm = warp >> 2, wn = warp & 3;    // 4 x 4 warp grid: 32 rows x 64 cols each
    int r4 = lane >> 2, c4 = lane & 3;

    float acc[2][8][4];
    #pragma unroll
    for (int mi = 0; mi < 2; mi++)
        #pragma unroll
        for (int j = 0; j < 8; j++)
            #pragma unroll
            for (int e = 0; e < 4; e++) acc[mi][j][e] = 0.f;

    // cp.async mapping: rows of 64B data (4 x 16B chunks) in 96B-stride smem rows
    int arow = tid >> 2, au = tid & 3;    // A: 512 chunks -> 1/thread (each of hi/lo)

    // prefetch k-tile 0
    {
        uint32_t adst = smb + (uint32_t)(arow * 96 + au * 16);
        size_t g = (size_t)arow * D_ + au * 8;
        cp16(adst,             Ahg + g);
        cp16(adst + 2 * A_T,   Alg + g);          // Alo region (bytes = A_T*2)
        #pragma unroll
        for (int i = 0; i < 2; i++) {             // B: 1024 chunks each -> 2/thread
            int c = tid + i * 512; int row = c >> 2, u = c & 3;
            uint32_t bdst = smb + 4 * A_T + (uint32_t)(row * 96 + u * 16);
            size_t gb = (size_t)row * D_ + u * 8;
            cp16(bdst,           Bhg + gb);
            cp16(bdst + 2 * B_T, Blg + gb);
        }
    }
    asm volatile("cp.async.commit_group;");

    const int KI = D_ / BKC;   // 16
    for (int kt = 0; kt < KI; kt++) {
        int buf = kt & 1;
        if (kt + 1 < KI) {
            int nb = buf ^ 1; int k0 = (kt + 1) * BKC;
            uint32_t base = smb + (uint32_t)nb * (BUF * 2);
            uint32_t adst = base + (uint32_t)(arow * 96 + au * 16);
            size_t g = (size_t)arow * D_ + k0 + au * 8;
            cp16(adst,           Ahg + g);
            cp16(adst + 2 * A_T, Alg + g);
            #pragma unroll
            for (int i = 0; i < 2; i++) {
                int c = tid + i * 512; int row = c >> 2, u = c & 3;
                uint32_t bdst = base + 4 * A_T + (uint32_t)(row * 96 + u * 16);
                size_t gb = (size_t)row * D_ + k0 + u * 8;
                cp16(bdst,           Bhg + gb);
                cp16(bdst + 2 * B_T, Blg + gb);
            }
            asm volatile("cp.async.commit_group;");
            asm volatile("cp.async.wait_group 1;");
        } else {
            asm volatile("cp.async.wait_group 0;");
        }
        __syncthreads();

        const __nv_bfloat16* Ah = sm + (size_t)buf * BUF + (wm * 32) * STRB;
        const __nv_bfloat16* Al = Ah + A_T;
        const __nv_bfloat16* Bh = sm + (size_t)buf * BUF + 2 * A_T + (wn * 64) * STRB;
        const __nv_bfloat16* Bl = Bh + B_T;
        #pragma unroll
        for (int s = 0; s < 2; s++) {             // two k16 steps per BKC=32
            int kq = s * 16 + c4 * 4;             // quad {2c4,2c4+1,2c4+8,2c4+9}
            uint2 ah0 = *reinterpret_cast<const uint2*>(&Ah[(r4)      * STRB + kq]);
            uint2 ah1 = *reinterpret_cast<const uint2*>(&Ah[(r4 + 8)  * STRB + kq]);
            uint2 ah2 = *reinterpret_cast<const uint2*>(&Ah[(r4 + 16) * STRB + kq]);
            uint2 ah3 = *reinterpret_cast<const uint2*>(&Ah[(r4 + 24) * STRB + kq]);
            uint2 al0 = *reinterpret_cast<const uint2*>(&Al[(r4)      * STRB + kq]);
            uint2 al1 = *reinterpret_cast<const uint2*>(&Al[(r4 + 8)  * STRB + kq]);
            uint2 al2 = *reinterpret_cast<const uint2*>(&Al[(r4 + 16) * STRB + kq]);
            uint2 al3 = *reinterpret_cast<const uint2*>(&Al[(r4 + 24) * STRB + kq]);
            #pragma unroll
            for (int j = 0; j < 8; j++) {
                int ro = (j * 8 + r4) * STRB + kq;
                uint2 bh = *reinterpret_cast<const uint2*>(&Bh[ro]);
                uint2 bl = *reinterpret_cast<const uint2*>(&Bl[ro]);
                // hi*hi + hi*lo + lo*hi
                mma_bf16(acc[0][j], ah0.x, ah1.x, ah0.y, ah1.y, bh.x, bh.y);
                mma_bf16(acc[0][j], ah0.x, ah1.x, ah0.y, ah1.y, bl.x, bl.y);
                mma_bf16(acc[0][j], al0.x, al1.x, al0.y, al1.y, bh.x, bh.y);
                mma_bf16(acc[1][j], ah2.x, ah3.x, ah2.y, ah3.y, bh.x, bh.y);
                mma_bf16(acc[1][j], ah2.x, ah3.x, ah2.y, ah3.y, bl.x, bl.y);
                mma_bf16(acc[1][j], al2.x, al3.x, al2.y, al3.y, bh.x, bh.y);
            }
        }
        __syncthreads();
    }

    // ---------------- fused epilogue ----------------
    float A0 = g_alpha[0], A1 = g_alpha[1], A2 = g_alpha[2];
    int colb = wn * 64 + c4 * 2;
    float sums[2][2] = {{0.f, 0.f}, {0.f, 0.f}};
    #pragma unroll
    for (int mi = 0; mi < 2; mi++) {
        int gr0 = t0 + wm * 32 + mi * 16 + r4;
        const float* W0 = g_W + (size_t)gr0 * R_;
        const float* W1 = W0 + 8 * R_;
        #pragma unroll
        for (int j = 0; j < 8; j++) {
            int col = colb + j * 8;
            float p;
            p = gphi(acc[mi][j][0], A0, A1, A2) * W0[col];     acc[mi][j][0] = p; sums[mi][0] += p;
            p = gphi(acc[mi][j][1], A0, A1, A2) * W0[col + 1]; acc[mi][j][1] = p; sums[mi][0] += p;
            p = gphi(acc[mi][j][2], A0, A1, A2) * W1[col];     acc[mi][j][2] = p; sums[mi][1] += p;
            p = gphi(acc[mi][j][3], A0, A1, A2) * W1[col + 1]; acc[mi][j][3] = p; sums[mi][1] += p;
        }
    }
    #pragma unroll
    for (int mi = 0; mi < 2; mi++)
        #pragma unroll
        for (int e = 0; e < 2; e++) {
            sums[mi][e] += __shfl_xor_sync(0xffffffffu, sums[mi][e], 1);
            sums[mi][e] += __shfl_xor_sync(0xffffffffu, sums[mi][e], 2);
        }
    if (c4 == 0) {
        #pragma unroll
        for (int mi = 0; mi < 2; mi++) {
            red[wn][wm * 32 + mi * 16 + r4]     = sums[mi][0];
            red[wn][wm * 32 + mi * 16 + r4 + 8] = sums[mi][1];
        }
    }
    __syncthreads();

    #pragma unroll
    for (int mi = 0; mi < 2; mi++) {
        #pragma unroll
        for (int e = 0; e < 2; e++) {
            int lrow = wm * 32 + mi * 16 + r4 + 8 * e;
            float tot = red[0][lrow] + red[1][lrow] + red[2][lrow] + red[3][lrow];
            float inv = 1.0f / fmaxf(tot, 1e-6f);
            float* o = out + ((size_t)b * T_ + t0 + lrow) * (R_ + 1);
            #pragma unroll
            for (int j = 0; j < 8; j++) {
                int col = colb + j * 8;
                o[col]     = acc[mi][j][2 * e]     * inv;
                o[col + 1] = acc[mi][j][2 * e + 1] * inv;
            }
            if (wn == 0 && c4 == 0) o[R_] = 1.0f;
        }
    }
}

// ---------------- launch ----------------
extern "C" void kernel_launch(void* const* d_in, const int* in_sizes, int n_in,
                              void* d_out, int out_size) {
    const float* z  = (const float*)d_in[0];
    const float* gw = (const float*)d_in[1];
    const float* ta = (const float*)d_in[2];
    float* out = (float*)d_out;

    prep_kernel<<<1, 256>>>(gw, ta);
    w_kernel<<<T_, R_>>>();
    norm_kernel<<<B_ * T_, 128>>>(z);
    gather_kernel<<<B_ * R_, 128>>>();

    cudaFuncSetAttribute(gemm_kernel, cudaFuncAttributeMaxDynamicSharedMemorySize, SMEM_BYTES);
    gemm_kernel<<<dim3(T_ / BM, B_), 512, SMEM_BYTES>>>(out);
}